// round 6
// baseline (speedup 1.0000x reference)
#include <cuda_runtime.h>
#include <cstdint>

// UpsampleNearest4D: x (2,8,8,16,64,64) f32, x2 on axes 2..5.
// Output (2,8,16,32,128,128).
//
// Input-driven, one thread per input float2, 8 x float4 {a,a,b,b} stores
// (proven best structure). R6 delta: split the t-duplicate across TWO
// launches. Kernel A writes the t-even slabs (and pulls the whole 32MiB
// input through L2 once); kernel B writes the t-odd slabs with reads
// served from L2 -> pure DRAM write stream, no read/write turnarounds.
// Zero added DRAM traffic. Stores are .cs (evict-first) so the write
// stream does not evict the L2-resident input between A and B.

__global__ __launch_bounds__(512) void upsample4d_half_kernel(
    const float2* __restrict__ in, float4* __restrict__ out, unsigned tslab)
{
    unsigned idx = blockIdx.x * 512u + threadIdx.x;   // [0, 4194304)

    unsigned x2 = idx & 31u;            // float2 column within input row
    unsigned r  = idx >> 5;
    unsigned y  = r & 63u;  r >>= 6;
    unsigned z  = r & 15u;  r >>= 4;
    unsigned t  = r & 7u;   r >>= 3;
    unsigned nc = r;                    // [0,16)

    float2 v = __ldg(&in[idx]);
    float4 o = make_float4(v.x, v.x, v.y, v.y);

    // Output strides in float4 units: row = 128/4 = 32
    const unsigned SY = 32u;                 // one output row (512B)
    const unsigned SZ = 128u * 32u;          // OY rows

    unsigned ot = 2u * t + tslab;            // even (A) or odd (B) slab
    unsigned base = ((((nc * 16u + ot) * 32u + 2u * z) * 128u + 2u * y) * 32u) + x2;

    float4* p0 = out + base;

    #define STCS(ptr) asm volatile( \
        "st.global.cs.v4.f32 [%0], {%1,%2,%3,%4};" \
        :: "l"(ptr), "f"(o.x), "f"(o.y), "f"(o.z), "f"(o.w) : "memory")

    STCS(p0);
    STCS(p0 + SY);
    STCS(p0 + SZ);
    STCS(p0 + SZ + SY);

    #undef STCS
}

extern "C" void kernel_launch(void* const* d_in, const int* in_sizes, int n_in,
                              void* d_out, int out_size)
{
    const float2* in = (const float2*)d_in[0];
    float4* out = (float4*)d_out;

    // 8,388,608 input floats -> 4,194,304 float2 threads per launch
    const unsigned n_threads = 8u * 1024u * 1024u / 2u;
    const unsigned blocks = n_threads / 512u;

    // A: t-even slabs; reads come from DRAM, input lands in L2.
    upsample4d_half_kernel<<<blocks, 512u>>>(in, out, 0u);
    // B: t-odd slabs; reads hit L2 -> pure DRAM write stream.
    upsample4d_half_kernel<<<blocks, 512u>>>(in, out, 1u);
}

// round 7
// speedup vs baseline: 1.0527x; 1.0527x over previous
#include <cuda_runtime.h>
#include <cstdint>

// UpsampleNearest4D: x (2,8,8,16,64,64) f32, x2 on axes 2..5.
// Output (2,8,16,32,128,128).
//
// Input-driven. R7: one thread per TWO input float2 from the same input
// row (cols x2 and x2+16), i.e. 2 front-batched LDG.64 then 16
// independent STG.128 {a,a,b,b}. Dose-response from R1/R6 shows DRAM%
// rises with per-thread outstanding stores (4->63.5%, 8->71.8%); this
// doubles the drain depth to 16 while keeping 16B store width (32B was
// worse, R2) and perfect per-instruction 128B-sector coverage.
//
// Input  (f2 units): NC=16, T=8,  Z=16, Y=64, row = 32 f2 (two 16-col halves)
// Output (f4 units): NC=16, OT=16, OZ=32, OY=128, row = 32 f4

__global__ __launch_bounds__(512) void upsample4d_kernel(
    const float2* __restrict__ in, float4* __restrict__ out)
{
    unsigned idx = blockIdx.x * 512u + threadIdx.x;   // [0, 2097152)

    unsigned xh = idx & 15u;            // column within row half
    unsigned r  = idx >> 4;
    unsigned y  = r & 63u;  r >>= 6;
    unsigned z  = r & 15u;  r >>= 4;
    unsigned t  = r & 7u;   r >>= 3;
    unsigned nc = r;                    // [0,16)

    unsigned irow = (((nc * 8u + t) * 16u + z) * 64u + y) * 32u;
    float2 va = __ldg(&in[irow + xh]);
    float2 vb = __ldg(&in[irow + xh + 16u]);

    float4 oa = make_float4(va.x, va.x, va.y, va.y);
    float4 ob = make_float4(vb.x, vb.x, vb.y, vb.y);

    // Output strides in float4 units: row = 128/4 = 32
    const unsigned SY = 32u;                 // one output row (512B)
    const unsigned SZ = 128u * 32u;          // OY rows
    const unsigned ST = 32u * 128u * 32u;    // OZ * OY rows

    unsigned base = ((((nc * 16u + 2u * t) * 32u + 2u * z) * 128u + 2u * y) * 32u) + xh;

    float4* p0 = out + base;
    float4* p1 = out + base + ST;

    #define STCS(ptr, v) asm volatile( \
        "st.global.cs.v4.f32 [%0], {%1,%2,%3,%4};" \
        :: "l"(ptr), "f"((v).x), "f"((v).y), "f"((v).z), "f"((v).w) : "memory")

    STCS(p0,                oa);  STCS(p0 + 16u,           ob);
    STCS(p0 + SY,           oa);  STCS(p0 + SY + 16u,      ob);
    STCS(p0 + SZ,           oa);  STCS(p0 + SZ + 16u,      ob);
    STCS(p0 + SZ + SY,      oa);  STCS(p0 + SZ + SY + 16u, ob);
    STCS(p1,                oa);  STCS(p1 + 16u,           ob);
    STCS(p1 + SY,           oa);  STCS(p1 + SY + 16u,      ob);
    STCS(p1 + SZ,           oa);  STCS(p1 + SZ + 16u,      ob);
    STCS(p1 + SZ + SY,      oa);  STCS(p1 + SZ + SY + 16u, ob);

    #undef STCS
}

extern "C" void kernel_launch(void* const* d_in, const int* in_sizes, int n_in,
                              void* d_out, int out_size)
{
    const float2* in = (const float2*)d_in[0];
    float4* out = (float4*)d_out;

    // 8,388,608 input floats -> 2,097,152 threads (2 float2 each)
    const unsigned n_threads = 8u * 1024u * 1024u / 4u;
    upsample4d_kernel<<<n_threads / 512u, 512u>>>(in, out);
}